// round 4
// baseline (speedup 1.0000x reference)
#include <cuda_runtime.h>
#include <cstdint>

#define NB 32       // batch
#define NS 8192     // seq len
#define ND 32       // hidden dim
#define NG 128      // 4*ND gates
#define NC 256      // output cats
#define CHUNK 32    // steps per producer->consumer handoff
#define NCHUNK (NS / CHUNK)
#define RING 64     // ring slots (2 chunks)
#define ROWB (ND * 4)   // bytes per ring row

#define B_READY 1
#define B_FREE  2
#define SYNC_CNT 288    // 32 scan + 256 consumer threads

__device__ __forceinline__ float tanh_fast(float x) {
    float y;
    asm("tanh.approx.f32 %0, %1;" : "=f"(y) : "f"(x));
    return y;
}
__device__ __forceinline__ uint64_t pack2(float lo, float hi) {
    uint64_t r;
    asm("mov.b64 %0, {%1, %2};" : "=l"(r) : "f"(lo), "f"(hi));
    return r;
}
__device__ __forceinline__ void unpack2(float& lo, float& hi, uint64_t v) {
    asm("mov.b64 {%0, %1}, %2;" : "=f"(lo), "=f"(hi) : "l"(v));
}
__device__ __forceinline__ void fma2(uint64_t& acc, uint64_t a, uint64_t b) {
    asm("fma.rn.f32x2 %0, %1, %2, %0;" : "+l"(acc) : "l"(a), "l"(b));
}
__device__ __forceinline__ uint64_t add2(uint64_t a, uint64_t b) {
    uint64_t r;
    asm("add.rn.f32x2 %0, %1, %2;" : "=l"(r) : "l"(a), "l"(b));
    return r;
}
__device__ __forceinline__ void bar_sync(int id, int cnt) {
    asm volatile("bar.sync %0, %1;" :: "r"(id), "r"(cnt) : "memory");
}
__device__ __forceinline__ void bar_arrive(int id, int cnt) {
    asm volatile("bar.arrive %0, %1;" :: "r"(id), "r"(cnt) : "memory");
}
__device__ __forceinline__ uint32_t smem_u32(const void* p) {
    uint32_t a;
    asm("{ .reg .u64 t; cvta.to.shared.u64 t, %1; cvt.u32.u64 %0, t; }"
        : "=r"(a) : "l"(p));
    return a;
}

// One block per batch, 384 threads (12 warps):
//   warp 11 (SMSP 3): single-warp LSTM scan. Lane l owns dim l and all 4 gate
//     columns (l, 32+l, 64+l, 96+l) -> gate mixing is lane-local, NO per-step
//     barrier/shuffle. h broadcast via intra-warp smem ring (in-order LSU).
//   warps 0,1,2,4,5,6,8,9 (SMSPs 0-2): epilogue consumers, 1 output col each.
//   warps 3,7,10: exit (keeps SMSP 3 scan-exclusive).
__global__ void __launch_bounds__(384, 1) fused_kernel(
    const float* __restrict__ x,      // (B, S)
    const float* __restrict__ bos,    // (D)
    const float* __restrict__ W_in,   // (1, D)
    const float* __restrict__ b_in,   // (D)
    const float* __restrict__ Wx,     // (D, 4D)
    const float* __restrict__ Wh,     // (D, 4D)
    const float* __restrict__ b_lstm, // (4D)
    const float* __restrict__ W_out,  // (D, C)
    const float* __restrict__ b_out,  // (C)
    float* __restrict__ out)          // (B, S, C)
{
    const int b    = blockIdx.x;
    const int tid  = threadIdx.x;
    const int wid  = tid >> 5;
    const int lane = tid & 31;

    __shared__ float hring[RING][ND];   // 8 KB: h history, doubles as scan ping-pong

    if (wid == 3 || wid == 7 || wid == 10) return;

    if (wid == 11) {
        // ───────────────────────── scan warp ─────────────────────────
        // packed Wh pairs per gate; sigmoid gates (i,f,o) pre-scaled by 0.5
        uint64_t whp[4][16];
        float u[4], v[4], zb[4];
#pragma unroll
        for (int g = 0; g < 4; g++) {
            const float ws  = (g == 2) ? 1.0f : 0.5f;
            const int   col = g * 32 + lane;
#pragma unroll
            for (int j = 0; j < 16; j++)
                whp[g][j] = pack2(ws * Wh[(2 * j) * NG + col],
                                  ws * Wh[(2 * j + 1) * NG + col]);
            float uu = 0.f, vv = 0.f, z0 = 0.f;
            for (int d = 0; d < ND; d++) {
                float wx = Wx[d * NG + col];
                uu = fmaf(W_in[d], wx, uu);
                vv = fmaf(b_in[d], wx, vv);
                z0 = fmaf(bos[d],  wx, z0);
            }
            float bl = b_lstm[col];
            u[g]  = ws * uu;
            v[g]  = ws * (vv + bl);
            zb[g] = ws * (z0 + bl);
        }

        const uint32_t base = smem_u32(hring);
        // init slot 63 (read by step 0)
        asm volatile("st.shared.f32 [%0], %1;"
                     :: "r"(base + 63 * ROWB + lane * 4), "f"(0.f) : "memory");

        float c = 0.f;
        const float* xb = x + (size_t)b * NS;
        uint32_t rd = base + 63 * ROWB;   // row read address (prev step's h)

        for (int n = 0; n < NCHUNK; n++) {
            if (n >= 2) bar_sync(B_FREE, SYNC_CNT);   // chunk n-2 consumed
            const int s0 = n * CHUNK;
#pragma unroll 2
            for (int s = s0; s < s0 + CHUNK; s++) {
                float xn = __ldg(xb + s);

                uint64_t hp[16];
#pragma unroll
                for (int j = 0; j < 8; j++)
                    asm volatile("ld.shared.v2.u64 {%0,%1}, [%2];"
                                 : "=l"(hp[2 * j]), "=l"(hp[2 * j + 1])
                                 : "r"(rd + j * 16));

                uint64_t a00 = pack2(zb[0], 0.f), a01 = pack2(0.f, 0.f);
                uint64_t a10 = pack2(zb[1], 0.f), a11 = pack2(0.f, 0.f);
                uint64_t a20 = pack2(zb[2], 0.f), a21 = pack2(0.f, 0.f);
                uint64_t a30 = pack2(zb[3], 0.f), a31 = pack2(0.f, 0.f);
#pragma unroll
                for (int j = 0; j < 8; j++) {
                    fma2(a00, hp[2 * j],     whp[0][2 * j]);
                    fma2(a01, hp[2 * j + 1], whp[0][2 * j + 1]);
                    fma2(a10, hp[2 * j],     whp[1][2 * j]);
                    fma2(a11, hp[2 * j + 1], whp[1][2 * j + 1]);
                    fma2(a20, hp[2 * j],     whp[2][2 * j]);
                    fma2(a21, hp[2 * j + 1], whp[2][2 * j + 1]);
                    fma2(a30, hp[2 * j],     whp[3][2 * j]);
                    fma2(a31, hp[2 * j + 1], whp[3][2 * j + 1]);
                }
                float lo, hi, zi, zf, zg, zo;
                unpack2(lo, hi, add2(a00, a01)); zi = lo + hi;
                unpack2(lo, hi, add2(a10, a11)); zf = lo + hi;
                unpack2(lo, hi, add2(a20, a21)); zg = lo + hi;
                unpack2(lo, hi, add2(a30, a31)); zo = lo + hi;

                float tg = tanh_fast(zg);
                float i_ = fmaf(0.5f, tanh_fast(zi), 0.5f);
                float f_ = fmaf(0.5f, tanh_fast(zf), 0.5f);
                float o_ = fmaf(0.5f, tanh_fast(zo), 0.5f);

                c = fmaf(f_, c, i_ * tg);
                float h = o_ * tanh_fast(c);

                uint32_t wslot = base + (uint32_t)(s & (RING - 1)) * ROWB;
                asm volatile("st.shared.f32 [%0], %1;"
                             :: "r"(wslot + lane * 4), "f"(h) : "memory");
                rd = wslot;

                zb[0] = fmaf(xn, u[0], v[0]);
                zb[1] = fmaf(xn, u[1], v[1]);
                zb[2] = fmaf(xn, u[2], v[2]);
                zb[3] = fmaf(xn, u[3], v[3]);
            }
            __threadfence_block();
            bar_arrive(B_READY, SYNC_CNT);            // publish chunk n
        }
        // drain: balance consumer arrivals for final two chunks
        bar_sync(B_FREE, SYNC_CNT);
        bar_sync(B_FREE, SYNC_CNT);
    } else {
        // ─────────────────────── consumer warps ───────────────────────
        const int rank = (wid < 3) ? wid : (wid < 7 ? wid - 1 : wid - 2);
        const int col  = rank * 32 + lane;

        uint64_t wv[16];
#pragma unroll
        for (int j = 0; j < 16; j++)
            wv[j] = pack2(W_out[(2 * j) * NC + col],
                          W_out[(2 * j + 1) * NC + col]);
        const float bias = b_out[col];
        float* ob = out + (size_t)b * NS * NC + col;

        for (int n = 0; n < NCHUNK; n++) {
            bar_sync(B_READY, SYNC_CNT);              // chunk n published
            const float* hbase = &hring[(n & 1) * CHUNK][0];
            float* orow = ob + (size_t)n * CHUNK * NC;
#pragma unroll 2
            for (int r = 0; r < CHUNK; r++) {
                const ulonglong2* hr = (const ulonglong2*)(hbase + r * ND);
                uint64_t acc0 = pack2(bias, 0.f), acc1 = pack2(0.f, 0.f);
#pragma unroll
                for (int j = 0; j < 8; j++) {
                    ulonglong2 q = hr[j];
                    fma2(acc0, q.x, wv[2 * j]);
                    fma2(acc1, q.y, wv[2 * j + 1]);
                }
                float lo, hi;
                unpack2(lo, hi, add2(acc0, acc1));
                orow[(size_t)r * NC] = lo + hi;
            }
            bar_arrive(B_FREE, SYNC_CNT);             // release chunk n
        }
    }
}

extern "C" void kernel_launch(void* const* d_in, const int* in_sizes, int n_in,
                              void* d_out, int out_size)
{
    const float* x      = (const float*)d_in[0];
    const float* bos    = (const float*)d_in[1];
    const float* W_in   = (const float*)d_in[2];
    const float* b_in   = (const float*)d_in[3];
    const float* Wx     = (const float*)d_in[4];
    const float* Wh     = (const float*)d_in[5];
    const float* b_lstm = (const float*)d_in[6];
    const float* W_out  = (const float*)d_in[7];
    const float* b_out  = (const float*)d_in[8];

    fused_kernel<<<NB, 384>>>(x, bos, W_in, b_in, Wx, Wh, b_lstm,
                              W_out, b_out, (float*)d_out);
}

// round 5
// speedup vs baseline: 1.4786x; 1.4786x over previous
#include <cuda_runtime.h>
#include <cstdint>

#define NB 32        // batch
#define NS 8192      // seq len
#define ND 32        // hidden dim
#define NG 128       // 4*ND gates
#define NC 256       // output cats
#define CHUNK 32     // steps per progress publish
#define NCHUNK (NS / CHUNK)        // 256
#define NWORK 116                  // worker blocks (148 - 32)
#define NITEM (NB * NCHUNK)        // 8192 work items

// h history (B, S, D) fp32 = 33.5 MB (fits in 126 MB L2) + progress flags
__device__ float g_hs[NB * NS * ND];
__device__ int   g_prog[NB];

__device__ __forceinline__ float tanh_fast(float x) {
    float y;
    asm("tanh.approx.f32 %0, %1;" : "=f"(y) : "f"(x));
    return y;
}
__device__ __forceinline__ uint64_t pack2(float lo, float hi) {
    uint64_t r;
    asm("mov.b64 %0, {%1, %2};" : "=l"(r) : "f"(lo), "f"(hi));
    return r;
}
__device__ __forceinline__ void unpack2(float& lo, float& hi, uint64_t v) {
    asm("mov.b64 {%0, %1}, %2;" : "=f"(lo), "=f"(hi) : "l"(v));
}
__device__ __forceinline__ void fma2(uint64_t& acc, uint64_t a, uint64_t b) {
    asm("fma.rn.f32x2 %0, %1, %2, %0;" : "+l"(acc) : "l"(a), "l"(b));
}
__device__ __forceinline__ uint64_t add2(uint64_t a, uint64_t b) {
    uint64_t r;
    asm("add.rn.f32x2 %0, %1, %2;" : "=l"(r) : "l"(a), "l"(b));
    return r;
}

__global__ void init_kernel() {
    if (threadIdx.x < NB) g_prog[threadIdx.x] = 0;
}

// grid = 148 blocks x 128 threads.
//   blocks 0..31   : LSTM scan for batch b (4 warps = 4 gates, lane = hidden dim)
//   blocks 32..147 : persistent epilogue workers, item = (batch, chunk of 32 steps)
// Scan never waits on workers (g_hs has no backpressure) -> deadlock-free.
__global__ void __launch_bounds__(128, 1) fused_kernel(
    const float* __restrict__ x,      // (B, S)
    const float* __restrict__ bos,    // (D)
    const float* __restrict__ W_in,   // (1, D)
    const float* __restrict__ b_in,   // (D)
    const float* __restrict__ Wx,     // (D, 4D)
    const float* __restrict__ Wh,     // (D, 4D)
    const float* __restrict__ b_lstm, // (4D)
    const float* __restrict__ W_out,  // (D, C)
    const float* __restrict__ b_out,  // (C)
    float* __restrict__ out)          // (B, S, C)
{
    const int bid = blockIdx.x;
    const int tid = threadIdx.x;

    if (bid < NB) {
        // ───────────────────────── scan block ─────────────────────────
        const int b = bid;
        const int w = tid >> 5;     // gate: 0=i 1=f 2=g 3=o
        const int l = tid & 31;     // hidden dim
        const int k = tid;          // gate column
        const bool sig = (w != 2);  // sigmoid gates: fold 0.5 pre-scale

        __shared__ float4 gbuf[2][32];     // [parity][dim] = {i,f,g,o}
        __shared__ float  hbuf[2][4][32];  // [parity][warp][dim] private h

        const float ws = sig ? 0.5f : 1.0f;
        uint64_t whp[16];
#pragma unroll
        for (int j = 0; j < 16; j++)
            whp[j] = pack2(ws * Wh[(2 * j) * NG + k],
                           ws * Wh[(2 * j + 1) * NG + k]);

        float u = 0.f, v = 0.f, z0 = 0.f;
#pragma unroll
        for (int d = 0; d < ND; d++) {
            float wx = Wx[d * NG + k];
            u  = fmaf(W_in[d], wx, u);
            v  = fmaf(b_in[d], wx, v);
            z0 = fmaf(bos[d],  wx, z0);
        }
        float bl = b_lstm[k];
        v  = ws * (v + bl);
        z0 = ws * (z0 + bl);
        u *= ws;

        float c = 0.f;
        hbuf[1][w][l] = 0.f;        // parity-0 step reads hbuf[1]
        float zbase = z0;
        const float* xb = x + (size_t)b * NS;
        float* hs_b = g_hs + (size_t)b * NS * ND + l;
        __syncthreads();

#define STEP(P, S_) do {                                                     \
        float xn = __ldg(xb + (S_));                                         \
        const ulonglong2* hp = (const ulonglong2*)hbuf[(P) ^ 1][w];          \
        uint64_t a0 = pack2(zbase, 0.f), a1 = pack2(0.f, 0.f);               \
        uint64_t a2 = pack2(0.f, 0.f),   a3 = pack2(0.f, 0.f);               \
        _Pragma("unroll")                                                    \
        for (int j = 0; j < 4; j++) {                                        \
            ulonglong2 q0 = hp[2 * j];                                       \
            ulonglong2 q1 = hp[2 * j + 1];                                   \
            fma2(a0, q0.x, whp[4 * j + 0]);                                  \
            fma2(a1, q0.y, whp[4 * j + 1]);                                  \
            fma2(a2, q1.x, whp[4 * j + 2]);                                  \
            fma2(a3, q1.y, whp[4 * j + 3]);                                  \
        }                                                                    \
        float lo, hi;                                                        \
        unpack2(lo, hi, add2(add2(a0, a1), add2(a2, a3)));                   \
        float z = lo + hi;                                                   \
        float t = tanh_fast(z);                                              \
        float act = sig ? fmaf(0.5f, t, 0.5f) : t;                           \
        ((float*)&gbuf[(P)][l])[w] = act;                                    \
        zbase = fmaf(xn, u, v);                                              \
        __syncthreads();                                                     \
        float4 g4 = gbuf[(P)][l];                                            \
        c = fmaf(g4.y, c, g4.x * g4.z);                                      \
        float h = g4.w * tanh_fast(c);                                       \
        hbuf[(P)][w][l] = h;                                                 \
        if (((S_) & 3) == w) hs_b[(size_t)(S_) * ND] = h;                    \
    } while (0)

        for (int n = 0; n < NCHUNK; n++) {
            const int s0 = n * CHUNK;
#pragma unroll 2
            for (int s = s0; s < s0 + CHUNK; s += 2) {
                STEP(0, s);
                STEP(1, s + 1);
            }
            __syncthreads();                     // all warps' STGs issued
            if (tid == 0) {
                __threadfence();                 // cumulative: make them visible
                asm volatile("st.global.release.gpu.s32 [%0], %1;"
                             :: "l"(&g_prog[b]), "r"(n + 1) : "memory");
            }
        }
#undef STEP
    } else {
        // ─────────────────────── worker block ───────────────────────
        const int wkr = bid - NB;
        __shared__ float tile[CHUNK * ND];       // 4 KB h tile
        __shared__ int   s_ready;

        // output cols: tid and tid+128; W_out columns register-resident
        const int c0 = tid, c1 = tid + 128;
        uint64_t wv0[16], wv1[16];
#pragma unroll
        for (int j = 0; j < 16; j++) {
            wv0[j] = pack2(W_out[(2 * j) * NC + c0], W_out[(2 * j + 1) * NC + c0]);
            wv1[j] = pack2(W_out[(2 * j) * NC + c1], W_out[(2 * j + 1) * NC + c1]);
        }
        const float bias0 = b_out[c0], bias1 = b_out[c1];

        for (int i = wkr; i < NITEM; i += NWORK) {
            const int b     = i & (NB - 1);
            const int chunk = i >> 5;

            if (tid == 0) {
                int cur;
                do {
                    asm volatile("ld.acquire.gpu.global.s32 %0, [%1];"
                                 : "=r"(cur) : "l"(&g_prog[b]) : "memory");
                    if (cur > chunk) break;
                    __nanosleep(128);
                } while (true);
                s_ready = cur;
            }
            __syncthreads();                     // flag acquire -> tile loads

            const float* src = g_hs + ((size_t)b * NS + (size_t)chunk * CHUNK) * ND;
#pragma unroll
            for (int q = 0; q < 2; q++)
                ((float4*)tile)[tid + 128 * q] = ((const float4*)src)[tid + 128 * q];
            __syncthreads();

            float* orow = out + ((size_t)b * NS + (size_t)chunk * CHUNK) * NC;
#pragma unroll 2
            for (int r = 0; r < CHUNK; r++) {
                const ulonglong2* hr = (const ulonglong2*)(tile + r * ND);
                uint64_t p0 = pack2(bias0, 0.f), p1 = pack2(0.f, 0.f);
                uint64_t q0 = pack2(bias1, 0.f), q1 = pack2(0.f, 0.f);
#pragma unroll
                for (int j = 0; j < 8; j++) {
                    ulonglong2 hv = hr[j];
                    fma2(p0, hv.x, wv0[2 * j]);
                    fma2(p1, hv.y, wv0[2 * j + 1]);
                    fma2(q0, hv.x, wv1[2 * j]);
                    fma2(q1, hv.y, wv1[2 * j + 1]);
                }
                float lo, hi, r0, r1;
                unpack2(lo, hi, add2(p0, p1)); r0 = lo + hi;
                unpack2(lo, hi, add2(q0, q1)); r1 = lo + hi;
                orow[(size_t)r * NC + c0] = r0;
                orow[(size_t)r * NC + c1] = r1;
            }
            __syncthreads();                     // tile reuse guard
        }
    }
}

extern "C" void kernel_launch(void* const* d_in, const int* in_sizes, int n_in,
                              void* d_out, int out_size)
{
    const float* x      = (const float*)d_in[0];
    const float* bos    = (const float*)d_in[1];
    const float* W_in   = (const float*)d_in[2];
    const float* b_in   = (const float*)d_in[3];
    const float* Wx     = (const float*)d_in[4];
    const float* Wh     = (const float*)d_in[5];
    const float* b_lstm = (const float*)d_in[6];
    const float* W_out  = (const float*)d_in[7];
    const float* b_out  = (const float*)d_in[8];

    init_kernel<<<1, 32>>>();
    fused_kernel<<<148, 128>>>(x, bos, W_in, b_in, Wx, Wh, b_lstm,
                               W_out, b_out, (float*)d_out);
}

// round 6
// speedup vs baseline: 1.6593x; 1.1222x over previous
#include <cuda_runtime.h>
#include <cstdint>

#define NB 32        // batch
#define NS 8192      // seq len
#define ND 32        // hidden dim
#define NG 128       // 4*ND gates
#define NC 256       // output cats
#define CHUNK 32     // steps per progress publish
#define NCHUNK (NS / CHUNK)        // 256
#define NWORK 116                  // worker blocks (148 - 32)
#define NITEM (NB * NCHUNK)        // 8192 work items

// h history (B, S, D) fp32 = 33.5 MB + progress flags
__device__ float g_hs[NB * NS * ND];
__device__ int   g_prog[NB];

__device__ __forceinline__ float tanh_fast(float x) {
    float y;
    asm("tanh.approx.f32 %0, %1;" : "=f"(y) : "f"(x));
    return y;
}
__device__ __forceinline__ uint64_t pack2(float lo, float hi) {
    uint64_t r;
    asm("mov.b64 %0, {%1, %2};" : "=l"(r) : "f"(lo), "f"(hi));
    return r;
}
__device__ __forceinline__ void unpack2(float& lo, float& hi, uint64_t v) {
    asm("mov.b64 {%0, %1}, %2;" : "=f"(lo), "=f"(hi) : "l"(v));
}
__device__ __forceinline__ void fma2(uint64_t& acc, uint64_t a, uint64_t b) {
    asm("fma.rn.f32x2 %0, %1, %2, %0;" : "+l"(acc) : "l"(a), "l"(b));
}
__device__ __forceinline__ uint64_t add2(uint64_t a, uint64_t b) {
    uint64_t r;
    asm("add.rn.f32x2 %0, %1, %2;" : "=l"(r) : "l"(a), "l"(b));
    return r;
}

__global__ void init_kernel() {
    if (threadIdx.x < NB) g_prog[threadIdx.x] = 0;
}

// grid = 148 x 128.  blocks 0..31: LSTM scan (4 warps = gates, lane = dim).
// blocks 32..147: persistent epilogue workers. Scan never waits on workers.
__global__ void __launch_bounds__(128, 1) fused_kernel(
    const float* __restrict__ x,      // (B, S)
    const float* __restrict__ bos,    // (D)
    const float* __restrict__ W_in,   // (1, D)
    const float* __restrict__ b_in,   // (D)
    const float* __restrict__ Wx,     // (D, 4D)
    const float* __restrict__ Wh,     // (D, 4D)
    const float* __restrict__ b_lstm, // (4D)
    const float* __restrict__ W_out,  // (D, C)
    const float* __restrict__ b_out,  // (C)
    float* __restrict__ out)          // (B, S, C)
{
    const int bid = blockIdx.x;
    const int tid = threadIdx.x;

    if (bid < NB) {
        // ───────────────────────── scan block ─────────────────────────
        const int b = bid;
        const int w = tid >> 5;     // gate: 0=i 1=f 2=g 3=o
        const int l = tid & 31;     // hidden dim
        const int k = tid;          // gate column
        const bool sig = (w != 2);  // sigmoid gates: fold 0.5 pre-scale

        __shared__ float4 gbuf[2][32];   // [parity][dim] = {i,f,g,o}
        __shared__ float  hbuf[4][32];   // [warp][dim] private h (single copy)

        const float ws = sig ? 0.5f : 1.0f;
        uint64_t whp[16];
#pragma unroll
        for (int j = 0; j < 16; j++)
            whp[j] = pack2(ws * Wh[(2 * j) * NG + k],
                           ws * Wh[(2 * j + 1) * NG + k]);

        float u = 0.f, v = 0.f, z0 = 0.f;
#pragma unroll
        for (int d = 0; d < ND; d++) {
            float wx = Wx[d * NG + k];
            u  = fmaf(W_in[d], wx, u);
            v  = fmaf(b_in[d], wx, v);
            z0 = fmaf(bos[d],  wx, z0);
        }
        float bl = b_lstm[k];
        v  = ws * (v + bl);
        z0 = ws * (z0 + bl);
        u *= ws;

        float c = 0.f;
        hbuf[w][l] = 0.f;           // step 0 reads zero h
        float zbase = z0;
        const float* xb = x + (size_t)b * NS;
        float* hs_b = g_hs + (size_t)b * NS * ND + l;
        __syncthreads();

        // P = gbuf parity (compile-time), J = position in chunk (compile-time)
#define STEP(P, J) do {                                                      \
        float xn = __shfl_sync(0xffffffffu, xv, (J));                        \
        const ulonglong2* hp = (const ulonglong2*)hbuf[w];                   \
        uint64_t a0 = pack2(zbase, 0.f), a1 = pack2(0.f, 0.f);               \
        uint64_t a2 = pack2(0.f, 0.f),   a3 = pack2(0.f, 0.f);               \
        _Pragma("unroll")                                                    \
        for (int j = 0; j < 4; j++) {                                        \
            ulonglong2 q0 = hp[2 * j];                                       \
            ulonglong2 q1 = hp[2 * j + 1];                                   \
            fma2(a0, q0.x, whp[4 * j + 0]);                                  \
            fma2(a1, q0.y, whp[4 * j + 1]);                                  \
            fma2(a2, q1.x, whp[4 * j + 2]);                                  \
            fma2(a3, q1.y, whp[4 * j + 3]);                                  \
        }                                                                    \
        float lo, hi;                                                        \
        unpack2(lo, hi, add2(add2(a0, a1), add2(a2, a3)));                   \
        float z = lo + hi;                                                   \
        float t = tanh_fast(z);                                              \
        float act = sig ? fmaf(0.5f, t, 0.5f) : t;                           \
        ((float*)&gbuf[(P)][l])[w] = act;                                    \
        zbase = fmaf(xn, u, v);                                              \
        __syncthreads();                                                     \
        float4 g4 = gbuf[(P)][l];                                            \
        c = fmaf(g4.y, c, g4.x * g4.z);                                      \
        float h = g4.w * tanh_fast(c);                                       \
        hbuf[w][l] = h;                                                      \
        if (w == ((J) & 3)) hs_b[(size_t)(s0 + (J)) * ND] = h;               \
    } while (0)

        for (int n = 0; n < NCHUNK; n++) {
            const int s0 = n * CHUNK;
            const float xv = __ldg(xb + s0 + l);   // chunk's x in lane regs
#pragma unroll
            for (int jj = 0; jj < CHUNK; jj += 4) {
                STEP(0, jj + 0);
                STEP(1, jj + 1);
                STEP(0, jj + 2);
                STEP(1, jj + 3);
            }
            __syncthreads();                     // all warps' STGs issued
            if (tid == 0) {
                __threadfence();                 // make chunk's h visible
                asm volatile("st.global.release.gpu.s32 [%0], %1;"
                             :: "l"(&g_prog[b]), "r"(n + 1) : "memory");
            }
        }
#undef STEP
    } else {
        // ─────────────────────── worker block ───────────────────────
        const int wkr = bid - NB;
        __shared__ float tile[CHUNK * ND];       // 4 KB h tile

        const int c0 = tid, c1 = tid + 128;
        uint64_t wv0[16], wv1[16];
#pragma unroll
        for (int j = 0; j < 16; j++) {
            wv0[j] = pack2(W_out[(2 * j) * NC + c0], W_out[(2 * j + 1) * NC + c0]);
            wv1[j] = pack2(W_out[(2 * j) * NC + c1], W_out[(2 * j + 1) * NC + c1]);
        }
        const float bias0 = b_out[c0], bias1 = b_out[c1];

        for (int i = wkr; i < NITEM; i += NWORK) {
            const int b     = i & (NB - 1);
            const int chunk = i >> 5;

            if (tid == 0) {
                int cur;
                do {
                    asm volatile("ld.acquire.gpu.global.s32 %0, [%1];"
                                 : "=r"(cur) : "l"(&g_prog[b]) : "memory");
                    if (cur > chunk) break;
                    __nanosleep(128);
                } while (true);
            }
            __syncthreads();                     // flag acquire -> tile loads

            const float* src = g_hs + ((size_t)b * NS + (size_t)chunk * CHUNK) * ND;
#pragma unroll
            for (int q = 0; q < 2; q++)
                ((float4*)tile)[tid + 128 * q] = ((const float4*)src)[tid + 128 * q];
            __syncthreads();

            float* orow = out + ((size_t)b * NS + (size_t)chunk * CHUNK) * NC;
#pragma unroll 2
            for (int r = 0; r < CHUNK; r++) {
                const ulonglong2* hr = (const ulonglong2*)(tile + r * ND);
                uint64_t p0 = pack2(bias0, 0.f), p1 = pack2(0.f, 0.f);
                uint64_t q0 = pack2(bias1, 0.f), q1 = pack2(0.f, 0.f);
#pragma unroll
                for (int j = 0; j < 8; j++) {
                    ulonglong2 hv = hr[j];
                    fma2(p0, hv.x, wv0[2 * j]);
                    fma2(p1, hv.y, wv0[2 * j + 1]);
                    fma2(q0, hv.x, wv1[2 * j]);
                    fma2(q1, hv.y, wv1[2 * j + 1]);
                }
                float lo, hi, r0, r1;
                unpack2(lo, hi, add2(p0, p1)); r0 = lo + hi;
                unpack2(lo, hi, add2(q0, q1)); r1 = lo + hi;
                orow[(size_t)r * NC + c0] = r0;
                orow[(size_t)r * NC + c1] = r1;
            }
            __syncthreads();                     // tile reuse guard
        }
    }
}

extern "C" void kernel_launch(void* const* d_in, const int* in_sizes, int n_in,
                              void* d_out, int out_size)
{
    const float* x      = (const float*)d_in[0];
    const float* bos    = (const float*)d_in[1];
    const float* W_in   = (const float*)d_in[2];
    const float* b_in   = (const float*)d_in[3];
    const float* Wx     = (const float*)d_in[4];
    const float* Wh     = (const float*)d_in[5];
    const float* b_lstm = (const float*)d_in[6];
    const float* W_out  = (const float*)d_in[7];
    const float* b_out  = (const float*)d_in[8];

    init_kernel<<<1, 32>>>();
    fused_kernel<<<148, 128>>>(x, bos, W_in, b_in, Wx, Wh, b_lstm,
                               W_out, b_out, (float*)d_out);
}